// round 12
// baseline (speedup 1.0000x reference)
#include <cuda_runtime.h>
#include <cuda_bf16.h>

#define THREADS 1024

// Dead-code-eliminated dataflow:
//   s   = relu(dot(inputs[row,:], W1) + b1)    -- only 70 rows matter
//   v   = relu(s * W2[col] + b2[col])
// Branch3 (blk=0..63): row=blk*64, col=1; h=relu(v*W3a+b3a);
//   out[t*5120+blk*80+j] = relu(h*W3b[j]+b3b[j])  for t=0..79, j=0..79
// Gap: out[409600..409663]=0  (folded into blk 64)
// Branch4 (blk=64..69): k=(blk-64)*4096+1; row=k/6; col=64+k%6;
//   h=relu(v*W4a+b4a); out[409664+(blk-64)*513+j]=relu(h*W4b[j]+b4b[j])

__global__ __launch_bounds__(THREADS, 1)
void hyper_pong_kernel(const float* __restrict__ inputs,
                       const float* __restrict__ W1,
                       const float* __restrict__ b1,
                       const float* __restrict__ W2,
                       const float* __restrict__ b2,
                       const float* __restrict__ W3a,
                       const float* __restrict__ b3a,
                       const float* __restrict__ W3b,
                       const float* __restrict__ b3b,
                       const float* __restrict__ W4a,
                       const float* __restrict__ b4a,
                       const float* __restrict__ W4b,
                       const float* __restrict__ b4b,
                       float* __restrict__ out)
{
    const int blk = blockIdx.x;
    const int tid = threadIdx.x;
    const bool is3 = (blk < 64);

    // ---- issue ALL epilogue loads first, so they overlap the big dot ----
    int row, col;
    if (is3) { row = blk * 64; col = 1; }
    else {
        int k = (blk - 64) * 4096 + 1;
        row = k / 6;
        col = 64 + (k % 6);
        if (blk == 64 && tid < 64) out[409600 + tid] = 0.0f;   // zero gap
    }

    const float sb1  = *b1;
    const float sw2  = W2[col];
    const float sb2  = b2[col];
    const float swA  = is3 ? *W3a : *W4a;
    const float sbA  = is3 ? *b3a : *b4a;

    // Per-thread epilogue weights.
    // Branch3: each thread stores float4 q0 = tid%20 (and q1 = (tid+1024)%20 if tid<576).
    // Branch4: thread tid<513 stores scalar j = tid.
    float4 w3b_0 = make_float4(0.f,0.f,0.f,0.f), b3b_0 = w3b_0;
    float4 w3b_1 = w3b_0, b3b_1 = w3b_0;
    float  w4s = 0.f, b4s = 0.f;
    int t0 = 0, q0 = 0, t1 = 0, q1 = 0;
    const bool two = (tid < 576);
    if (is3) {
        t0 = tid / 20;  q0 = tid - t0 * 20;
        const float4* w3v = reinterpret_cast<const float4*>(W3b);
        const float4* b3v = reinterpret_cast<const float4*>(b3b);
        w3b_0 = w3v[q0];  b3b_0 = b3v[q0];
        if (two) {
            int idx1 = tid + 1024;
            t1 = idx1 / 20;  q1 = idx1 - t1 * 20;
            w3b_1 = w3v[q1];  b3b_1 = b3v[q1];
        }
    } else if (tid < 513) {
        w4s = W4b[tid];  b4s = b4b[tid];
    }

    // ---- dot(inputs[row], W1): 1600 float4 pairs ----
    const float4* ip = reinterpret_cast<const float4*>(inputs + (size_t)row * 6400);
    const float4* wp = reinterpret_cast<const float4*>(W1);

    float4 a0 = ip[tid];
    float4 w0 = wp[tid];
    float4 a1, w1;
    if (two) { a1 = ip[tid + 1024]; w1 = wp[tid + 1024]; }
    float acc = a0.x * w0.x + a0.y * w0.y + a0.z * w0.z + a0.w * w0.w;
    if (two)
        acc += a1.x * w1.x + a1.y * w1.y + a1.z * w1.z + a1.w * w1.w;

    // ---- butterfly all-reduce: every thread ends with the total ----
    __shared__ float sred[32];
    #pragma unroll
    for (int off = 16; off > 0; off >>= 1)
        acc += __shfl_xor_sync(0xffffffffu, acc, off);
    if ((tid & 31) == 0) sred[tid >> 5] = acc;
    __syncthreads();
    float s = sred[tid & 31];
    #pragma unroll
    for (int off = 16; off > 0; off >>= 1)
        s += __shfl_xor_sync(0xffffffffu, s, off);

    // ---- scalar chain (all preloaded; every thread computes it) ----
    s = fmaxf(s + sb1, 0.0f);                     // layer 1 + relu
    float v = fmaxf(fmaf(s, sw2, sb2), 0.0f);     // layer 2 + relu
    const float h = fmaxf(fmaf(v, swA, sbA), 0.0f);

    if (is3) {
        // epilogue entirely in registers -> STG.128, no smem, no extra syncs
        float4 o0;
        o0.x = fmaxf(fmaf(h, w3b_0.x, b3b_0.x), 0.0f);
        o0.y = fmaxf(fmaf(h, w3b_0.y, b3b_0.y), 0.0f);
        o0.z = fmaxf(fmaf(h, w3b_0.z, b3b_0.z), 0.0f);
        o0.w = fmaxf(fmaf(h, w3b_0.w, b3b_0.w), 0.0f);
        float4* outv = reinterpret_cast<float4*>(out + blk * 80);
        outv[t0 * 1280 + q0] = o0;                 // 1280 = 5120/4
        if (two) {
            float4 o1;
            o1.x = fmaxf(fmaf(h, w3b_1.x, b3b_1.x), 0.0f);
            o1.y = fmaxf(fmaf(h, w3b_1.y, b3b_1.y), 0.0f);
            o1.z = fmaxf(fmaf(h, w3b_1.z, b3b_1.z), 0.0f);
            o1.w = fmaxf(fmaf(h, w3b_1.w, b3b_1.w), 0.0f);
            outv[t1 * 1280 + q1] = o1;
        }
    } else if (tid < 513) {
        out[409664 + (blk - 64) * 513 + tid] = fmaxf(fmaf(h, w4s, b4s), 0.0f);
    }
}

extern "C" void kernel_launch(void* const* d_in, const int* in_sizes, int n_in,
                              void* d_out, int out_size)
{
    const float* inputs = (const float*)d_in[0];
    const float* W1     = (const float*)d_in[1];
    const float* b1     = (const float*)d_in[2];
    const float* W2     = (const float*)d_in[3];
    const float* b2     = (const float*)d_in[4];
    const float* W3a    = (const float*)d_in[5];
    const float* b3a    = (const float*)d_in[6];
    const float* W3b    = (const float*)d_in[7];
    const float* b3b    = (const float*)d_in[8];
    const float* W4a    = (const float*)d_in[9];
    const float* b4a    = (const float*)d_in[10];
    const float* W4b    = (const float*)d_in[11];
    const float* b4b    = (const float*)d_in[12];
    float* out = (float*)d_out;

    hyper_pong_kernel<<<70, THREADS>>>(inputs, W1, b1, W2, b2,
                                       W3a, b3a, W3b, b3b,
                                       W4a, b4a, W4b, b4b, out);
}